// round 2
// baseline (speedup 1.0000x reference)
#include <cuda_runtime.h>
#include <math.h>

#define B_   32
#define C_   2048
#define T_   16
#define S_   49
#define H_   512
#define HID_ 1024
#define OUT_ 101

// ---------------- device scratch (no allocations allowed) ----------------
__device__ __align__(16) float g_pooled[B_ * C_];
__device__ __align__(16) float g_hidh[B_ * HID_];
__device__ __align__(16) float g_hidc[B_ * HID_];
__device__ __align__(16) float g_h[2][B_ * H_];
__device__ __align__(16) float g_c[B_ * H_];
__device__ __align__(16) float g_ctx[B_ * C_];
__device__ __align__(16) float g_hsum[B_ * H_];

__device__ __forceinline__ float warp_sum(float v) {
    #pragma unroll
    for (int o = 16; o; o >>= 1) v += __shfl_xor_sync(0xFFFFFFFFu, v, o);
    return v;
}

__device__ __forceinline__ float sigmoidf_(float x) {
    return 1.0f / (1.0f + expf(-x));
}

// ---------------- pooling: pooled[b][c] = mean over T*S (784 contiguous) ----
__global__ __launch_bounds__(256) void k_pool(const float* __restrict__ x) {
    int wid  = (blockIdx.x * blockDim.x + threadIdx.x) >> 5;   // 0 .. B*C-1
    int lane = threadIdx.x & 31;
    const float4* p = (const float4*)(x + (size_t)wid * (T_ * S_)); // 196 float4
    float s = 0.f;
    #pragma unroll 7
    for (int i = lane; i < 196; i += 32) {
        float4 v = p[i];
        s += v.x + v.y + v.z + v.w;
    }
    s = warp_sum(s);
    if (lane == 0) g_pooled[wid] = s * (1.0f / 784.0f);
}

// ---------------- layer0 of h0/c0 MLP: (B,C)->(B,1024), both paths ----------
__global__ __launch_bounds__(256) void k_layer0(
    const float* __restrict__ w_h, const float* __restrict__ b_h,
    const float* __restrict__ w_c, const float* __restrict__ b_c) {
    int wid  = (blockIdx.x * blockDim.x + threadIdx.x) >> 5;  // 0..65535
    int lane = threadIdx.x & 31;
    int path = wid >> 15;            // 0 = h-path, 1 = c-path
    int r    = wid & 32767;          // b*1024 + k
    int b    = r >> 10;
    int k    = r & 1023;
    const float* w = path ? w_c : w_h;
    const float4* wp = (const float4*)(w + (size_t)k * C_);       // 512 f4
    const float4* pp = (const float4*)(g_pooled + b * C_);
    float acc = 0.f;
    #pragma unroll 4
    for (int i = lane; i < C_ / 4; i += 32) {
        float4 a = pp[i], ww = wp[i];
        acc += a.x * ww.x + a.y * ww.y + a.z * ww.z + a.w * ww.w;
    }
    acc = warp_sum(acc);
    if (lane == 0) {
        float bias = path ? b_c[k] : b_h[k];
        (path ? g_hidc : g_hidh)[r] = acc + bias;
    }
}

// ---------------- layer1: (B,1024)->(B,512) for h0 and c0; zero hsum --------
__global__ __launch_bounds__(256) void k_layer1(
    const float* __restrict__ w_h, const float* __restrict__ b_h,
    const float* __restrict__ w_c, const float* __restrict__ b_c) {
    int wid  = (blockIdx.x * blockDim.x + threadIdx.x) >> 5;  // 0..32767
    int lane = threadIdx.x & 31;
    int path = wid >> 14;
    int r    = wid & 16383;         // b*512 + j
    int b    = r >> 9;
    int j    = r & 511;
    const float* w   = path ? w_c : w_h;
    const float* src = path ? g_hidc : g_hidh;
    const float4* wp = (const float4*)(w + (size_t)j * HID_);     // 256 f4
    const float4* sp = (const float4*)(src + b * HID_);
    float acc = 0.f;
    #pragma unroll 8
    for (int i = lane; i < HID_ / 4; i += 32) {
        float4 a = sp[i], ww = wp[i];
        acc += a.x * ww.x + a.y * ww.y + a.z * ww.z + a.w * ww.w;
    }
    acc = warp_sum(acc);
    if (lane == 0) {
        float bias = path ? b_c[j] : b_h[j];
        if (path == 0) { g_h[0][r] = acc + bias; g_hsum[r] = 0.f; }
        else           { g_c[r]    = acc + bias; }
    }
}

// ---------------- per step: attention softmax + context + alpha output ------
// grid = B * 8 chunks, block = 256. Each block redundantly computes alpha for
// its b (cheap: 49 dots of 512), then its 256-channel slice of ctx.
__global__ __launch_bounds__(256) void k_attn_ctx(
    const float* __restrict__ x, const float* __restrict__ att_w,
    float* __restrict__ alpha_out, int t, int hsel) {
    int b     = blockIdx.x >> 3;
    int chunk = blockIdx.x & 7;
    __shared__ float sh_h[H_];
    __shared__ float sh_e[S_];
    __shared__ float sh_alpha[S_];
    int tid = threadIdx.x;

    for (int i = tid; i < H_; i += 256) sh_h[i] = g_h[hsel][b * H_ + i];
    __syncthreads();

    int wid = tid >> 5, lane = tid & 31;
    const float4* hh = (const float4*)sh_h;
    for (int s = wid; s < S_; s += 8) {
        const float4* wr = (const float4*)(att_w + (size_t)s * H_);  // 128 f4
        float acc = 0.f;
        #pragma unroll 4
        for (int i = lane; i < H_ / 4; i += 32) {
            float4 a = hh[i], w4 = wr[i];
            acc += a.x * w4.x + a.y * w4.y + a.z * w4.z + a.w * w4.w;
        }
        acc = warp_sum(acc);
        if (lane == 0) sh_e[s] = acc;
    }
    __syncthreads();

    if (tid == 0) {
        float m = sh_e[0];
        #pragma unroll
        for (int s = 1; s < S_; s++) m = fmaxf(m, sh_e[s]);
        float sum = 0.f;
        #pragma unroll
        for (int s = 0; s < S_; s++) { float e = expf(sh_e[s] - m); sh_alpha[s] = e; sum += e; }
        float inv = 1.0f / sum;
        #pragma unroll
        for (int s = 0; s < S_; s++) sh_alpha[s] *= inv;
    }
    __syncthreads();

    if (chunk == 0 && tid < S_)
        alpha_out[((size_t)b * T_ + t) * S_ + tid] = sh_alpha[tid];

    // context: ctx[b][c] = sum_s alpha[s] * x[b][c][t][s]
    int c = chunk * 256 + tid;
    const float* fp = x + (((size_t)(b * C_ + c) * T_) + t) * S_;
    float acc = 0.f;
    #pragma unroll
    for (int s = 0; s < S_; s++) acc += sh_alpha[s] * __ldg(fp + s);
    g_ctx[b * C_ + c] = acc;
}

// ---------------- per step: 4 gates + LSTM cell update + hidden-sum ---------
// warp per (b, hidx): 4 dot products of length C (ih) + H (hh), then cell.
__global__ __launch_bounds__(256) void k_gates(
    const float* __restrict__ w_ih, const float* __restrict__ b_ih,
    const float* __restrict__ w_hh, const float* __restrict__ b_hh,
    int hsel) {
    int gwid = (blockIdx.x * blockDim.x + threadIdx.x) >> 5;  // 0..16383
    int lane = threadIdx.x & 31;
    int b = gwid >> 9;
    int j = gwid & 511;

    const float4* ctx4 = (const float4*)(g_ctx + b * C_);        // 512 f4
    const float4* h4   = (const float4*)(g_h[hsel] + b * H_);    // 128 f4
    const float4* wi0 = (const float4*)(w_ih + (size_t)(j)          * C_);
    const float4* wi1 = (const float4*)(w_ih + (size_t)(j + 512)    * C_);
    const float4* wi2 = (const float4*)(w_ih + (size_t)(j + 1024)   * C_);
    const float4* wi3 = (const float4*)(w_ih + (size_t)(j + 1536)   * C_);
    const float4* wh0 = (const float4*)(w_hh + (size_t)(j)          * H_);
    const float4* wh1 = (const float4*)(w_hh + (size_t)(j + 512)    * H_);
    const float4* wh2 = (const float4*)(w_hh + (size_t)(j + 1024)   * H_);
    const float4* wh3 = (const float4*)(w_hh + (size_t)(j + 1536)   * H_);

    float a0 = 0.f, a1 = 0.f, a2 = 0.f, a3 = 0.f;
    #pragma unroll 4
    for (int i = lane; i < C_ / 4; i += 32) {
        float4 cv = ctx4[i];
        float4 w;
        w = wi0[i]; a0 += cv.x * w.x + cv.y * w.y + cv.z * w.z + cv.w * w.w;
        w = wi1[i]; a1 += cv.x * w.x + cv.y * w.y + cv.z * w.z + cv.w * w.w;
        w = wi2[i]; a2 += cv.x * w.x + cv.y * w.y + cv.z * w.z + cv.w * w.w;
        w = wi3[i]; a3 += cv.x * w.x + cv.y * w.y + cv.z * w.z + cv.w * w.w;
    }
    #pragma unroll 4
    for (int i = lane; i < H_ / 4; i += 32) {
        float4 hv = h4[i];
        float4 w;
        w = wh0[i]; a0 += hv.x * w.x + hv.y * w.y + hv.z * w.z + hv.w * w.w;
        w = wh1[i]; a1 += hv.x * w.x + hv.y * w.y + hv.z * w.z + hv.w * w.w;
        w = wh2[i]; a2 += hv.x * w.x + hv.y * w.y + hv.z * w.z + hv.w * w.w;
        w = wh3[i]; a3 += hv.x * w.x + hv.y * w.y + hv.z * w.z + hv.w * w.w;
    }
    a0 = warp_sum(a0); a1 = warp_sum(a1); a2 = warp_sum(a2); a3 = warp_sum(a3);

    if (lane == 0) {
        float gi = a0 + b_ih[j]        + b_hh[j];
        float gf = a1 + b_ih[j + 512]  + b_hh[j + 512];
        float gg = a2 + b_ih[j + 1024] + b_hh[j + 1024];
        float go = a3 + b_ih[j + 1536] + b_hh[j + 1536];
        float iv = sigmoidf_(gi);
        float fv = sigmoidf_(gf);
        float gv = tanhf(gg);
        float ov = sigmoidf_(go);
        int idx = b * H_ + j;
        float cn = fv * g_c[idx] + iv * gv;
        g_c[idx] = cn;
        float hn = ov * tanhf(cn);
        g_h[hsel ^ 1][idx] = hn;
        g_hsum[idx] += hn;
    }
}

// ---------------- final: out[b][o] = (hsum[b] . W_out[o]) / T + bias --------
__global__ __launch_bounds__(256) void k_final(
    const float* __restrict__ fc_out_w, const float* __restrict__ fc_out_b,
    float* __restrict__ out) {
    int gwid = (blockIdx.x * blockDim.x + threadIdx.x) >> 5;  // 0..3231
    int lane = threadIdx.x & 31;
    if (gwid >= B_ * OUT_) return;
    int b = gwid / OUT_;
    int o = gwid % OUT_;
    const float4* wp = (const float4*)(fc_out_w + (size_t)o * H_);  // 128 f4
    const float4* hp = (const float4*)(g_hsum + b * H_);
    float acc = 0.f;
    #pragma unroll 4
    for (int i = lane; i < H_ / 4; i += 32) {
        float4 a = hp[i], w = wp[i];
        acc += a.x * w.x + a.y * w.y + a.z * w.z + a.w * w.w;
    }
    acc = warp_sum(acc);
    if (lane == 0) out[gwid] = acc * (1.0f / (float)T_) + fc_out_b[o];
}

// ---------------- launch ----------------------------------------------------
extern "C" void kernel_launch(void* const* d_in, const int* in_sizes, int n_in,
                              void* d_out, int out_size) {
    const float* input_x   = (const float*)d_in[0];
    const float* att_hw_w  = (const float*)d_in[1];
    const float* fc_h0_0_w = (const float*)d_in[2];
    const float* fc_h0_0_b = (const float*)d_in[3];
    const float* fc_h0_1_w = (const float*)d_in[4];
    const float* fc_h0_1_b = (const float*)d_in[5];
    const float* fc_c0_0_w = (const float*)d_in[6];
    const float* fc_c0_0_b = (const float*)d_in[7];
    const float* fc_c0_1_w = (const float*)d_in[8];
    const float* fc_c0_1_b = (const float*)d_in[9];
    const float* w_ih      = (const float*)d_in[10];
    const float* b_ih      = (const float*)d_in[11];
    const float* w_hh      = (const float*)d_in[12];
    const float* b_hh      = (const float*)d_in[13];
    const float* fc_out_w  = (const float*)d_in[14];
    const float* fc_out_b  = (const float*)d_in[15];

    float* out       = (float*)d_out;                 // final_output: B*OUT
    float* alpha_out = out + B_ * OUT_;               // alpha_total: B*T*S

    // pooling: B*C warps, 8 warps/block
    k_pool<<<(B_ * C_) / 8, 256>>>(input_x);
    // h0/c0 layer 0: 2*B*1024 warps
    k_layer0<<<(2 * B_ * HID_) / 8, 256>>>(fc_h0_0_w, fc_h0_0_b, fc_c0_0_w, fc_c0_0_b);
    // h0/c0 layer 1: 2*B*512 warps (+ zero hsum)
    k_layer1<<<(2 * B_ * H_) / 8, 256>>>(fc_h0_1_w, fc_h0_1_b, fc_c0_1_w, fc_c0_1_b);

    for (int t = 0; t < T_; t++) {
        int hsel = t & 1;
        k_attn_ctx<<<B_ * 8, 256>>>(input_x, att_hw_w, alpha_out, t, hsel);
        k_gates<<<(B_ * H_) / 8, 256>>>(w_ih, b_ih, w_hh, b_hh, hsel);
    }

    // final output GEMV: B*OUT warps
    k_final<<<(B_ * OUT_ + 7) / 8, 256>>>(fc_out_w, fc_out_b, out);
}

// round 3
// speedup vs baseline: 1.0623x; 1.0623x over previous
#include <cuda_runtime.h>
#include <math.h>

#define B_    32
#define C_    2048
#define T_    16
#define S_    49
#define H_    512
#define HID_  1024
#define OUT_  101
#define ROWS_ 2048      // 4*H gate rows
#define KTOT_ 2560      // C + H
#define KSPLIT_ 32
#define KC_   80        // KTOT_/KSPLIT_

// ---------------- device scratch ----------------
__device__ __align__(16) float g_Wt[KTOT_ * ROWS_];            // 20MB, [k][row]
__device__ __align__(16) float g_A[KTOT_ * B_];                // [k][b]: ctx rows 0..2047, h rows 2048..2559
__device__ __align__(16) float g_part[KSPLIT_ * B_ * ROWS_];   // 8MB, [split][b][row]
__device__ __align__(16) float g_pooled[B_ * C_];
__device__ __align__(16) float g_hidh[B_ * HID_];
__device__ __align__(16) float g_hidc[B_ * HID_];
__device__ __align__(16) float g_h0[B_ * H_];
__device__ __align__(16) float g_c[B_ * H_];
__device__ __align__(16) float g_hsum[B_ * H_];
__device__ __align__(16) float g_alpha[B_ * 64];               // padded to 64

__device__ __forceinline__ float warp_sum(float v) {
    #pragma unroll
    for (int o = 16; o; o >>= 1) v += __shfl_xor_sync(0xFFFFFFFFu, v, o);
    return v;
}
__device__ __forceinline__ float sigmoidf_(float x) {
    return 1.0f / (1.0f + expf(-x));
}

// ---------------- weight transpose: g_Wt[k][row] -------------------------
__global__ __launch_bounds__(256) void k_transpose_w(
    const float* __restrict__ wih, const float* __restrict__ whh) {
    __shared__ float s[32][33];
    int k0 = blockIdx.x * 32;
    int r0 = blockIdx.y * 32;
    int tx = threadIdx.x & 31, ty = threadIdx.x >> 5;  // ty: 0..7
    #pragma unroll
    for (int i = 0; i < 4; i++) {
        int row = r0 + ty + 8 * i;
        int k   = k0 + tx;
        float v = (k < C_) ? wih[(size_t)row * C_ + k]
                           : whh[(size_t)row * H_ + (k - C_)];
        s[ty + 8 * i][tx] = v;
    }
    __syncthreads();
    #pragma unroll
    for (int i = 0; i < 4; i++) {
        int k = k0 + ty + 8 * i;
        g_Wt[(size_t)k * ROWS_ + r0 + tx] = s[tx][ty + 8 * i];
    }
}

// ---------------- pooling (streaming loads) ------------------------------
__global__ __launch_bounds__(256) void k_pool(const float* __restrict__ x) {
    int wid  = (blockIdx.x * blockDim.x + threadIdx.x) >> 5;   // 0 .. B*C-1
    int lane = threadIdx.x & 31;
    const float4* p = (const float4*)(x + (size_t)wid * (T_ * S_)); // 196 f4
    float s = 0.f;
    #pragma unroll 7
    for (int i = lane; i < 196; i += 32) {
        float4 v = __ldcs(p + i);
        s += v.x + v.y + v.z + v.w;
    }
    s = warp_sum(s);
    if (lane == 0) g_pooled[wid] = s * (1.0f / 784.0f);
}

// ---------------- h0/c0 MLP layer 0 --------------------------------------
__global__ __launch_bounds__(256) void k_layer0(
    const float* __restrict__ w_h, const float* __restrict__ b_h,
    const float* __restrict__ w_c, const float* __restrict__ b_c) {
    int wid  = (blockIdx.x * blockDim.x + threadIdx.x) >> 5;
    int lane = threadIdx.x & 31;
    int path = wid >> 15;
    int r    = wid & 32767;
    int b    = r >> 10;
    int k    = r & 1023;
    const float* w = path ? w_c : w_h;
    const float4* wp = (const float4*)(w + (size_t)k * C_);
    const float4* pp = (const float4*)(g_pooled + b * C_);
    float acc = 0.f;
    #pragma unroll 4
    for (int i = lane; i < C_ / 4; i += 32) {
        float4 a = pp[i], ww = wp[i];
        acc += a.x * ww.x + a.y * ww.y + a.z * ww.z + a.w * ww.w;
    }
    acc = warp_sum(acc);
    if (lane == 0) {
        float bias = path ? b_c[k] : b_h[k];
        (path ? g_hidc : g_hidh)[r] = acc + bias;
    }
}

// ---------------- h0/c0 MLP layer 1 (writes h0 both layouts, zeros hsum) --
__global__ __launch_bounds__(256) void k_layer1(
    const float* __restrict__ w_h, const float* __restrict__ b_h,
    const float* __restrict__ w_c, const float* __restrict__ b_c) {
    int wid  = (blockIdx.x * blockDim.x + threadIdx.x) >> 5;
    int lane = threadIdx.x & 31;
    int path = wid >> 14;
    int r    = wid & 16383;
    int b    = r >> 9;
    int j    = r & 511;
    const float* w   = path ? w_c : w_h;
    const float* src = path ? g_hidc : g_hidh;
    const float4* wp = (const float4*)(w + (size_t)j * HID_);
    const float4* sp = (const float4*)(src + b * HID_);
    float acc = 0.f;
    #pragma unroll 8
    for (int i = lane; i < HID_ / 4; i += 32) {
        float4 a = sp[i], ww = wp[i];
        acc += a.x * ww.x + a.y * ww.y + a.z * ww.z + a.w * ww.w;
    }
    acc = warp_sum(acc);
    if (lane == 0) {
        float bias = path ? b_c[j] : b_h[j];
        float v = acc + bias;
        if (path == 0) {
            g_h0[r] = v;
            g_A[(size_t)(C_ + j) * B_ + b] = v;   // transposed h for GEMM
            g_hsum[r] = 0.f;
        } else {
            g_c[r] = v;
        }
    }
}

// ---------------- initial alpha from h0 ----------------------------------
__global__ __launch_bounds__(256) void k_alpha_init(
    const float* __restrict__ att_w, float* __restrict__ alpha_out) {
    int b = blockIdx.x;
    __shared__ float sh_h[H_];
    __shared__ float sh_e[56];
    int tid = threadIdx.x, warp = tid >> 5, lane = tid & 31;
    for (int i = tid; i < H_; i += 256) sh_h[i] = g_h0[b * H_ + i];
    __syncthreads();
    for (int s = warp; s < S_; s += 8) {
        float acc = 0.f;
        #pragma unroll
        for (int i = 0; i < 16; i++)
            acc += sh_h[lane + 32 * i] * __ldg(att_w + (size_t)s * H_ + lane + 32 * i);
        acc = warp_sum(acc);
        if (lane == 0) sh_e[s] = acc;
    }
    __syncthreads();
    if (warp == 0) {
        float e1 = sh_e[lane];
        float e2 = (lane < 17) ? sh_e[lane + 32] : -1e30f;
        float m = fmaxf(e1, e2);
        #pragma unroll
        for (int o = 16; o; o >>= 1) m = fmaxf(m, __shfl_xor_sync(0xFFFFFFFFu, m, o));
        float p1 = expf(e1 - m);
        float p2 = (lane < 17) ? expf(e2 - m) : 0.f;
        float sum = warp_sum(p1 + p2);
        float inv = 1.0f / sum;
        p1 *= inv; p2 *= inv;
        g_alpha[b * 64 + lane] = p1;
        alpha_out[((size_t)b * T_ + 0) * S_ + lane] = p1;
        if (lane < 17) {
            g_alpha[b * 64 + 32 + lane] = p2;
            alpha_out[((size_t)b * T_ + 0) * S_ + 32 + lane] = p2;
        }
    }
}

// ---------------- per step: context (lane-coalesced over S) --------------
__global__ __launch_bounds__(256) void k_ctx(const float* __restrict__ x, int t) {
    int gw   = blockIdx.x * 8 + (threadIdx.x >> 5);   // 0..4095
    int lane = threadIdx.x & 31;
    int b     = gw >> 7;            // 128 warps per b
    int cbase = (gw & 127) << 4;    // 16 channels per warp
    float a1 = g_alpha[b * 64 + lane];
    float a2 = (lane < 17) ? g_alpha[b * 64 + 32 + lane] : 0.f;
    #pragma unroll 4
    for (int cc = 0; cc < 16; cc++) {
        int c = cbase + cc;
        const float* base = x + (((size_t)(b * C_ + c) * T_) + t) * S_;
        float p = a1 * __ldcs(base + lane);
        if (lane < 17) p += a2 * __ldcs(base + 32 + lane);
        p = warp_sum(p);
        if (lane == 0) g_A[(size_t)c * B_ + b] = p;
    }
}

// ---------------- per step: gates GEMM (split-K outer product) -----------
// grid = 256: rt = blockIdx&7 (256 rows each), ks = blockIdx>>3 (K chunk 80)
__global__ __launch_bounds__(256) void k_gates() {
    int rt = blockIdx.x & 7;
    int ks = blockIdx.x >> 3;
    int warp = threadIdx.x >> 5, lane = threadIdx.x & 31;
    int rg = lane >> 2, bg = lane & 3;
    int r0 = rt * 256 + warp * 32 + rg * 4;   // 4 consecutive rows
    int b0 = bg * 8;                           // 8 consecutive batches
    const float4* W4 = (const float4*)g_Wt;
    const float4* A4 = (const float4*)g_A;
    float acc[4][8];
    #pragma unroll
    for (int i = 0; i < 4; i++)
        #pragma unroll
        for (int j = 0; j < 8; j++) acc[i][j] = 0.f;

    int k0 = ks * KC_;
    #pragma unroll 4
    for (int kk = 0; kk < KC_; kk++) {
        int k = k0 + kk;
        float4 wv  = W4[((size_t)k * ROWS_ + r0) >> 2];
        float4 av0 = A4[((size_t)k * B_ + b0) >> 2];
        float4 av1 = A4[((size_t)k * B_ + b0 + 4) >> 2];
        float w[4] = {wv.x, wv.y, wv.z, wv.w};
        float a[8] = {av0.x, av0.y, av0.z, av0.w, av1.x, av1.y, av1.z, av1.w};
        #pragma unroll
        for (int i = 0; i < 4; i++)
            #pragma unroll
            for (int j = 0; j < 8; j++)
                acc[i][j] = fmaf(w[i], a[j], acc[i][j]);
    }
    #pragma unroll
    for (int j = 0; j < 8; j++) {
        float4 o = make_float4(acc[0][j], acc[1][j], acc[2][j], acc[3][j]);
        *(float4*)&g_part[((size_t)(ks * B_ + b0 + j) * ROWS_) + r0] = o;
    }
}

// ---------------- per step: reduce + LSTM cell + next alpha ---------------
__global__ __launch_bounds__(512) void k_cell(
    const float* __restrict__ b_ih, const float* __restrict__ b_hh,
    const float* __restrict__ att_w, float* __restrict__ alpha_out, int t) {
    int b = blockIdx.x;
    int j = threadIdx.x;     // 0..511
    float gi = 0.f, gf = 0.f, gg = 0.f, go = 0.f;
    #pragma unroll 8
    for (int s = 0; s < KSPLIT_; s++) {
        const float* p = g_part + (size_t)(s * B_ + b) * ROWS_;
        gi += p[j];
        gf += p[512 + j];
        gg += p[1024 + j];
        go += p[1536 + j];
    }
    gi += b_ih[j]        + b_hh[j];
    gf += b_ih[512 + j]  + b_hh[512 + j];
    gg += b_ih[1024 + j] + b_hh[1024 + j];
    go += b_ih[1536 + j] + b_hh[1536 + j];

    float iv = sigmoidf_(gi);
    float fv = sigmoidf_(gf);
    float gv = tanhf(gg);
    float ov = sigmoidf_(go);
    int idx = b * H_ + j;
    float cn = fv * g_c[idx] + iv * gv;
    g_c[idx] = cn;
    float hn = ov * tanhf(cn);
    g_A[(size_t)(C_ + j) * B_ + b] = hn;   // transposed h for next GEMM
    g_hsum[idx] += hn;

    __shared__ float sh_h[H_];
    __shared__ float sh_e[56];
    sh_h[j] = hn;
    __syncthreads();

    if (t < T_ - 1) {
        int warp = j >> 5, lane = j & 31;
        for (int s = warp; s < S_; s += 16) {
            float acc = 0.f;
            #pragma unroll
            for (int i = 0; i < 16; i++)
                acc += sh_h[lane + 32 * i] * __ldg(att_w + (size_t)s * H_ + lane + 32 * i);
            acc = warp_sum(acc);
            if (lane == 0) sh_e[s] = acc;
        }
        __syncthreads();
        if (warp == 0) {
            float e1 = sh_e[lane];
            float e2 = (lane < 17) ? sh_e[lane + 32] : -1e30f;
            float m = fmaxf(e1, e2);
            #pragma unroll
            for (int o = 16; o; o >>= 1) m = fmaxf(m, __shfl_xor_sync(0xFFFFFFFFu, m, o));
            float p1 = expf(e1 - m);
            float p2 = (lane < 17) ? expf(e2 - m) : 0.f;
            float sum = warp_sum(p1 + p2);
            float inv = 1.0f / sum;
            p1 *= inv; p2 *= inv;
            g_alpha[b * 64 + lane] = p1;
            alpha_out[((size_t)b * T_ + (t + 1)) * S_ + lane] = p1;
            if (lane < 17) {
                g_alpha[b * 64 + 32 + lane] = p2;
                alpha_out[((size_t)b * T_ + (t + 1)) * S_ + 32 + lane] = p2;
            }
        }
    }
}

// ---------------- final output GEMV ---------------------------------------
__global__ __launch_bounds__(256) void k_final(
    const float* __restrict__ fc_out_w, const float* __restrict__ fc_out_b,
    float* __restrict__ out) {
    int gwid = (blockIdx.x * blockDim.x + threadIdx.x) >> 5;
    int lane = threadIdx.x & 31;
    if (gwid >= B_ * OUT_) return;
    int b = gwid / OUT_;
    int o = gwid % OUT_;
    const float4* wp = (const float4*)(fc_out_w + (size_t)o * H_);
    const float4* hp = (const float4*)(g_hsum + b * H_);
    float acc = 0.f;
    #pragma unroll 4
    for (int i = lane; i < H_ / 4; i += 32) {
        float4 a = hp[i], w = wp[i];
        acc += a.x * w.x + a.y * w.y + a.z * w.z + a.w * w.w;
    }
    acc = warp_sum(acc);
    if (lane == 0) out[gwid] = acc * (1.0f / (float)T_) + fc_out_b[o];
}

// ---------------- launch ----------------------------------------------------
extern "C" void kernel_launch(void* const* d_in, const int* in_sizes, int n_in,
                              void* d_out, int out_size) {
    const float* input_x   = (const float*)d_in[0];
    const float* att_hw_w  = (const float*)d_in[1];
    const float* fc_h0_0_w = (const float*)d_in[2];
    const float* fc_h0_0_b = (const float*)d_in[3];
    const float* fc_h0_1_w = (const float*)d_in[4];
    const float* fc_h0_1_b = (const float*)d_in[5];
    const float* fc_c0_0_w = (const float*)d_in[6];
    const float* fc_c0_0_b = (const float*)d_in[7];
    const float* fc_c0_1_w = (const float*)d_in[8];
    const float* fc_c0_1_b = (const float*)d_in[9];
    const float* w_ih      = (const float*)d_in[10];
    const float* b_ih      = (const float*)d_in[11];
    const float* w_hh      = (const float*)d_in[12];
    const float* b_hh      = (const float*)d_in[13];
    const float* fc_out_w  = (const float*)d_in[14];
    const float* fc_out_b  = (const float*)d_in[15];

    float* out       = (float*)d_out;
    float* alpha_out = out + B_ * OUT_;

    k_transpose_w<<<dim3(KTOT_ / 32, ROWS_ / 32), 256>>>(w_ih, w_hh);
    k_pool<<<(B_ * C_) / 8, 256>>>(input_x);
    k_layer0<<<(2 * B_ * HID_) / 8, 256>>>(fc_h0_0_w, fc_h0_0_b, fc_c0_0_w, fc_c0_0_b);
    k_layer1<<<(2 * B_ * H_) / 8, 256>>>(fc_h0_1_w, fc_h0_1_b, fc_c0_1_w, fc_c0_1_b);
    k_alpha_init<<<B_, 256>>>(att_hw_w, alpha_out);

    for (int t = 0; t < T_; t++) {
        k_ctx<<<512, 256>>>(input_x, t);
        k_gates<<<256, 256>>>();
        k_cell<<<B_, 512>>>(b_ih, b_hh, att_hw_w, alpha_out, t);
    }

    k_final<<<(B_ * OUT_ + 7) / 8, 256>>>(fc_out_w, fc_out_b, out);
}

// round 6
// speedup vs baseline: 1.4396x; 1.3551x over previous
#include <cuda_runtime.h>
#include <math.h>

#define B_    32
#define C_    2048
#define T_    16
#define S_    49
#define H_    512
#define HID_  1024
#define OUT_  101
#define M_    2048      // gate rows (= 4*H) and layer0 rows (1024h+1024c)
#define KTOT_ 2560      // C + H

// ---------------- device scratch ----------------
__device__ __align__(16) float g_xt[T_ * B_ * S_ * C_];        // 205MB [t][b][s][c]
__device__ __align__(16) float g_Wt[KTOT_ * M_];               // 20MB gates W^T [k][row]
__device__ __align__(16) float g_Wt0[C_ * M_];                 // 16MB layer0 W^T [k][row]
__device__ __align__(16) float g_A[KTOT_ * B_];                // [k][b] activations
__device__ __align__(16) float g_A0[C_ * B_];                  // pooled^T [k][b]
__device__ __align__(16) float g_part[16 * B_ * M_];           // 4MB split-K partials
__device__ __align__(16) float g_poolsum[B_ * C_];
__device__ __align__(16) float g_hidh[B_ * HID_];
__device__ __align__(16) float g_hidc[B_ * HID_];
__device__ __align__(16) float g_h0[B_ * H_];
__device__ __align__(16) float g_c[B_ * H_];
__device__ __align__(16) float g_hsum[B_ * H_];
__device__ __align__(16) float g_alpha[B_ * 64];

__device__ __forceinline__ float warp_sum(float v) {
    #pragma unroll
    for (int o = 16; o; o >>= 1) v += __shfl_xor_sync(0xFFFFFFFFu, v, o);
    return v;
}
__device__ __forceinline__ float sigmoidf_(float x) {
    return 1.0f / (1.0f + expf(-x));
}

// ---------------- transpose gate weights: g_Wt[k][row] --------------------
__global__ __launch_bounds__(256) void k_tw_gates(
    const float* __restrict__ wih, const float* __restrict__ whh) {
    __shared__ float s[32][33];
    int k0 = blockIdx.x * 32;
    int r0 = blockIdx.y * 32;
    int tx = threadIdx.x & 31, ty = threadIdx.x >> 5;
    #pragma unroll
    for (int i = 0; i < 4; i++) {
        int row = r0 + ty + 8 * i;
        int k   = k0 + tx;
        float v = (k < C_) ? wih[(size_t)row * C_ + k]
                           : whh[(size_t)row * H_ + (k - C_)];
        s[ty + 8 * i][tx] = v;
    }
    __syncthreads();
    #pragma unroll
    for (int i = 0; i < 4; i++) {
        int k = k0 + ty + 8 * i;
        g_Wt[(size_t)k * M_ + r0 + tx] = s[tx][ty + 8 * i];
    }
}

// ---------------- transpose layer0 weights (+ zero poolsum) ---------------
__global__ __launch_bounds__(256) void k_tw0(
    const float* __restrict__ w_h, const float* __restrict__ w_c) {
    int bid = blockIdx.y * gridDim.x + blockIdx.x;
    if (bid < (B_ * C_) / 256) g_poolsum[bid * 256 + threadIdx.x] = 0.f;
    __shared__ float s[32][33];
    int k0 = blockIdx.x * 32;
    int r0 = blockIdx.y * 32;
    int tx = threadIdx.x & 31, ty = threadIdx.x >> 5;
    #pragma unroll
    for (int i = 0; i < 4; i++) {
        int row = r0 + ty + 8 * i;
        int k   = k0 + tx;
        float v = (row < HID_) ? w_h[(size_t)row * C_ + k]
                               : w_c[(size_t)(row - HID_) * C_ + k];
        s[ty + 8 * i][tx] = v;
    }
    __syncthreads();
    #pragma unroll
    for (int i = 0; i < 4; i++) {
        int k = k0 + ty + 8 * i;
        g_Wt0[(size_t)k * M_ + r0 + tx] = s[tx][ty + 8 * i];
    }
}

// ---------------- x transpose to [t][b][s][c] + pooling partials ---------
__global__ __launch_bounds__(256) void k_xt(const float* __restrict__ x) {
    __shared__ float sm[64][51];
    int c0 = blockIdx.x * 64;
    int t  = blockIdx.y;
    int b  = blockIdx.z;
    int w = threadIdx.x >> 5, lane = threadIdx.x & 31;
    #pragma unroll
    for (int rr = 0; rr < 8; rr++) {
        int cc = w * 8 + rr;
        int c  = c0 + cc;
        const float* src = x + (((size_t)(b * C_ + c) * T_) + t) * S_;
        float v1 = __ldcs(src + lane);
        float v2 = (lane < S_ - 32) ? __ldcs(src + 32 + lane) : 0.f;
        sm[cc][lane] = v1;
        if (lane < S_ - 32) sm[cc][32 + lane] = v2;
        float s = warp_sum(v1 + v2);
        if (lane == 0) atomicAdd(&g_poolsum[b * C_ + c], s);
    }
    __syncthreads();
    size_t base = ((size_t)(t * B_ + b) * S_) * C_ + c0;
    for (int idx = threadIdx.x; idx < S_ * 64; idx += 256) {
        int s = idx >> 6, cc = idx & 63;
        g_xt[base + (size_t)s * C_ + cc] = sm[cc][s];
    }
}

// ---------------- pooled^T with scaling -----------------------------------
__global__ __launch_bounds__(256) void k_poolA() {
    int idx = blockIdx.x * 256 + threadIdx.x;   // b*C + k
    int b = idx >> 11, k = idx & 2047;
    g_A0[(size_t)k * B_ + b] = g_poolsum[idx] * (1.0f / 784.0f);
}

// ---------------- generic split-K GEMM: part[ks][b][row] ------------------
// SEL=0: layer0 (W=g_Wt0, A=g_A0, KC=128); SEL=1: gates (W=g_Wt, A=g_A, KC=160)
// grid 128 = 8 row-tiles x 16 k-splits; thread: 4 rows x 8 batches
template<int SEL>
__global__ __launch_bounds__(256) void k_gemm() {
    constexpr int KC = SEL ? 160 : 128;
    const float* __restrict__ Wt = SEL ? g_Wt : g_Wt0;
    const float* __restrict__ A  = SEL ? g_A  : g_A0;
    __shared__ float sA[160 * 32];
    int rt = blockIdx.x & 7;
    int ks = blockIdx.x >> 3;
    int k0 = ks * KC;
    for (int i = threadIdx.x; i < (KC * 32) / 4; i += 256)
        ((float4*)sA)[i] = ((const float4*)(A + (size_t)k0 * 32))[i];
    __syncthreads();

    int w = threadIdx.x >> 5, lane = threadIdx.x & 31;
    int r0 = rt * 256 + w * 32 + (lane >> 2) * 4;
    int b0 = (lane & 3) * 8;

    float acc[4][8];
    #pragma unroll
    for (int i = 0; i < 4; i++)
        #pragma unroll
        for (int j = 0; j < 8; j++) acc[i][j] = 0.f;

    const float* wp = Wt + (size_t)k0 * M_ + r0;
    const float* ap = sA + b0;
    #pragma unroll 4
    for (int kk = 0; kk < KC; kk++) {
        float4 wv  = *(const float4*)(wp + (size_t)kk * M_);
        float4 av0 = *(const float4*)(ap + kk * 32);
        float4 av1 = *(const float4*)(ap + kk * 32 + 4);
        float wf[4] = {wv.x, wv.y, wv.z, wv.w};
        float af[8] = {av0.x, av0.y, av0.z, av0.w, av1.x, av1.y, av1.z, av1.w};
        #pragma unroll
        for (int i = 0; i < 4; i++)
            #pragma unroll
            for (int j = 0; j < 8; j++)
                acc[i][j] = fmaf(wf[i], af[j], acc[i][j]);
    }
    #pragma unroll
    for (int j = 0; j < 8; j++) {
        int b = b0 + j;
        float4 o = make_float4(acc[0][j], acc[1][j], acc[2][j], acc[3][j]);
        *(float4*)&g_part[((size_t)(ks * B_ + b) * M_) + r0] = o;
    }
}

// ---------------- layer0 reduce: partials + bias -> hid[b][k] -------------
__global__ __launch_bounds__(256) void k_red0(
    const float* __restrict__ b_h, const float* __restrict__ b_c) {
    int gid = blockIdx.x * 256 + threadIdx.x;   // b*2048 + r
    int b = gid >> 11, r = gid & 2047;
    float s = 0.f;
    #pragma unroll
    for (int ks = 0; ks < 16; ks++) s += g_part[((size_t)(ks * B_ + b) * M_) + r];
    if (r < HID_) g_hidh[b * HID_ + r] = s + b_h[r];
    else          g_hidc[b * HID_ + (r - HID_)] = s + b_c[r - HID_];
}

// ---------------- layer1 (small, warp-per-output) -------------------------
__global__ __launch_bounds__(256) void k_layer1(
    const float* __restrict__ w_h, const float* __restrict__ b_h,
    const float* __restrict__ w_c, const float* __restrict__ b_c) {
    int wid  = (blockIdx.x * blockDim.x + threadIdx.x) >> 5;
    int lane = threadIdx.x & 31;
    int path = wid >> 14;
    int r    = wid & 16383;
    int b    = r >> 9;
    int j    = r & 511;
    const float* w   = path ? w_c : w_h;
    const float* src = path ? g_hidc : g_hidh;
    const float4* wp = (const float4*)(w + (size_t)j * HID_);
    const float4* sp = (const float4*)(src + b * HID_);
    float acc = 0.f;
    #pragma unroll 8
    for (int i = lane; i < HID_ / 4; i += 32) {
        float4 a = sp[i], ww = wp[i];
        acc += a.x * ww.x + a.y * ww.y + a.z * ww.z + a.w * ww.w;
    }
    acc = warp_sum(acc);
    if (lane == 0) {
        float bias = path ? b_c[j] : b_h[j];
        float v = acc + bias;
        if (path == 0) {
            g_h0[r] = v;
            g_A[(size_t)(C_ + j) * B_ + b] = v;
            g_hsum[r] = 0.f;
        } else {
            g_c[r] = v;
        }
    }
}

// ---------------- initial alpha from h0 ------------------------------------
__global__ __launch_bounds__(256) void k_alpha_init(
    const float* __restrict__ att_w, float* __restrict__ alpha_out) {
    int b = blockIdx.x;
    __shared__ float sh_h[H_];
    __shared__ float sh_e[56];
    int tid = threadIdx.x, warp = tid >> 5, lane = tid & 31;
    for (int i = tid; i < H_; i += 256) sh_h[i] = g_h0[b * H_ + i];
    __syncthreads();
    for (int s = warp; s < S_; s += 8) {
        float acc = 0.f;
        #pragma unroll
        for (int i = 0; i < 16; i++)
            acc += sh_h[lane + 32 * i] * __ldg(att_w + (size_t)s * H_ + lane + 32 * i);
        acc = warp_sum(acc);
        if (lane == 0) sh_e[s] = acc;
    }
    __syncthreads();
    if (warp == 0) {
        float e1 = sh_e[lane];
        float e2 = (lane < 17) ? sh_e[lane + 32] : -1e30f;
        float m = fmaxf(e1, e2);
        #pragma unroll
        for (int o = 16; o; o >>= 1) m = fmaxf(m, __shfl_xor_sync(0xFFFFFFFFu, m, o));
        float p1 = expf(e1 - m);
        float p2 = (lane < 17) ? expf(e2 - m) : 0.f;
        float sum = warp_sum(p1 + p2);
        float inv = 1.0f / sum;
        p1 *= inv; p2 *= inv;
        g_alpha[b * 64 + lane] = p1;
        alpha_out[((size_t)b * T_) * S_ + lane] = p1;
        if (lane < 17) {
            g_alpha[b * 64 + 32 + lane] = p2;
            alpha_out[((size_t)b * T_) * S_ + 32 + lane] = p2;
        }
    }
}

// ---------------- per step: context from g_xt (coalesced) ------------------
__global__ __launch_bounds__(256) void k_ctx(int t) {
    int b = blockIdx.x >> 2;
    int q = blockIdx.x & 3;
    __shared__ float sal[S_];
    if (threadIdx.x < S_) sal[threadIdx.x] = g_alpha[b * 64 + threadIdx.x];
    __syncthreads();
    int c = q * 512 + threadIdx.x * 2;
    const float* base = g_xt + ((size_t)(t * B_ + b) * S_) * C_ + c;
    float ax = 0.f, ay = 0.f;
    #pragma unroll 7
    for (int s = 0; s < S_; s++) {
        float2 v = __ldcs((const float2*)(base + (size_t)s * C_));
        float a = sal[s];
        ax = fmaf(a, v.x, ax);
        ay = fmaf(a, v.y, ay);
    }
    g_A[(size_t)c * B_ + b]       = ax;
    g_A[(size_t)(c + 1) * B_ + b] = ay;
}

// ---------------- per step: reduce + LSTM cell + next alpha ----------------
__global__ __launch_bounds__(512) void k_cell(
    const float* __restrict__ b_ih, const float* __restrict__ b_hh,
    const float* __restrict__ att_w, float* __restrict__ alpha_out, int t) {
    int b = blockIdx.x;
    int j = threadIdx.x;
    float gi = 0.f, gf = 0.f, gg = 0.f, go = 0.f;
    #pragma unroll
    for (int s = 0; s < 16; s++) {
        const float* p = g_part + (size_t)(s * B_ + b) * M_;
        gi += p[j];
        gf += p[512 + j];
        gg += p[1024 + j];
        go += p[1536 + j];
    }
    gi += b_ih[j]        + b_hh[j];
    gf += b_ih[512 + j]  + b_hh[512 + j];
    gg += b_ih[1024 + j] + b_hh[1024 + j];
    go += b_ih[1536 + j] + b_hh[1536 + j];

    float iv = sigmoidf_(gi);
    float fv = sigmoidf_(gf);
    float gv = tanhf(gg);
    float ov = sigmoidf_(go);
    int idx = b * H_ + j;
    float cn = fv * g_c[idx] + iv * gv;
    g_c[idx] = cn;
    float hn = ov * tanhf(cn);
    g_A[(size_t)(C_ + j) * B_ + b] = hn;
    g_hsum[idx] += hn;

    __shared__ float sh_h[H_];
    __shared__ float sh_e[56];
    sh_h[j] = hn;
    __syncthreads();

    if (t < T_ - 1) {
        int warp = j >> 5, lane = j & 31;
        for (int s = warp; s < S_; s += 16) {
            float acc = 0.f;
            #pragma unroll
            for (int i = 0; i < 16; i++)
                acc += sh_h[lane + 32 * i] * __ldg(att_w + (size_t)s * H_ + lane + 32 * i);
            acc = warp_sum(acc);
            if (lane == 0) sh_e[s] = acc;
        }
        __syncthreads();
        if (warp == 0) {
            float e1 = sh_e[lane];
            float e2 = (lane < 17) ? sh_e[lane + 32] : -1e30f;
            float m = fmaxf(e1, e2);
            #pragma unroll
            for (int o = 16; o; o >>= 1) m = fmaxf(m, __shfl_xor_sync(0xFFFFFFFFu, m, o));
            float p1 = expf(e1 - m);
            float p2 = (lane < 17) ? expf(e2 - m) : 0.f;
            float sum = warp_sum(p1 + p2);
            float inv = 1.0f / sum;
            p1 *= inv; p2 *= inv;
            g_alpha[b * 64 + lane] = p1;
            alpha_out[((size_t)b * T_ + (t + 1)) * S_ + lane] = p1;
            if (lane < 17) {
                g_alpha[b * 64 + 32 + lane] = p2;
                alpha_out[((size_t)b * T_ + (t + 1)) * S_ + 32 + lane] = p2;
            }
        }
    }
}

// ---------------- final output GEMV ----------------------------------------
__global__ __launch_bounds__(256) void k_final(
    const float* __restrict__ fc_out_w, const float* __restrict__ fc_out_b,
    float* __restrict__ out) {
    int gwid = (blockIdx.x * blockDim.x + threadIdx.x) >> 5;
    int lane = threadIdx.x & 31;
    if (gwid >= B_ * OUT_) return;
    int b = gwid / OUT_;
    int o = gwid % OUT_;
    const float4* wp = (const float4*)(fc_out_w + (size_t)o * H_);
    const float4* hp = (const float4*)(g_hsum + b * H_);
    float acc = 0.f;
    #pragma unroll 4
    for (int i = lane; i < H_ / 4; i += 32) {
        float4 a = hp[i], w = wp[i];
        acc += a.x * w.x + a.y * w.y + a.z * w.z + a.w * w.w;
    }
    acc = warp_sum(acc);
    if (lane == 0) out[gwid] = acc * (1.0f / (float)T_) + fc_out_b[o];
}

// ---------------- launch ----------------------------------------------------
extern "C" void kernel_launch(void* const* d_in, const int* in_sizes, int n_in,
                              void* d_out, int out_size) {
    const float* input_x   = (const float*)d_in[0];
    const float* att_hw_w  = (const float*)d_in[1];
    const float* fc_h0_0_w = (const float*)d_in[2];
    const float* fc_h0_0_b = (const float*)d_in[3];
    const float* fc_h0_1_w = (const float*)d_in[4];
    const float* fc_h0_1_b = (const float*)d_in[5];
    const float* fc_c0_0_w = (const float*)d_in[6];
    const float* fc_c0_0_b = (const float*)d_in[7];
    const float* fc_c0_1_w = (const float*)d_in[8];
    const float* fc_c0_1_b = (const float*)d_in[9];
    const float* w_ih      = (const float*)d_in[10];
    const float* b_ih      = (const float*)d_in[11];
    const float* w_hh      = (const float*)d_in[12];
    const float* b_hh      = (const float*)d_in[13];
    const float* fc_out_w  = (const float*)d_in[14];
    const float* fc_out_b  = (const float*)d_in[15];

    float* out       = (float*)d_out;
    float* alpha_out = out + B_ * OUT_;

    k_tw_gates<<<dim3(KTOT_ / 32, M_ / 32), 256>>>(w_ih, w_hh);
    k_tw0<<<dim3(C_ / 32, M_ / 32), 256>>>(fc_h0_0_w, fc_c0_0_w);
    k_xt<<<dim3(C_ / 64, T_, B_), 256>>>(input_x);
    k_poolA<<<(B_ * C_) / 256, 256>>>();
    k_gemm<0><<<128, 256>>>();               // layer0 GEMM
    k_red0<<<(B_ * M_) / 256, 256>>>(fc_h0_0_b, fc_c0_0_b);
    k_layer1<<<(2 * B_ * H_) / 8, 256>>>(fc_h0_1_w, fc_h0_1_b, fc_c0_1_w, fc_c0_1_b);
    k_alpha_init<<<B_, 256>>>(att_hw_w, alpha_out);

    for (int t = 0; t < T_; t++) {
        k_ctx<<<B_ * 4, 256>>>(t);
        k_gemm<1><<<128, 256>>>();           // gates GEMM
        k_cell<<<B_, 512>>>(b_ih, b_hh, att_hw_w, alpha_out, t);
    }

    k_final<<<(B_ * OUT_ + 7) / 8, 256>>>(fc_out_w, fc_out_b, out);
}